// round 1
// baseline (speedup 1.0000x reference)
#include <cuda_runtime.h>
#include <cstdint>
#include <cstddef>

// Problem constants
#define B   64
#define P   2048
#define PD  16
#define N   32
#define D   32
#define ND  1024          // N*D
#define CH  64            // p's per chunk in pass kernel
#define NCH 32            // P / CH

// Scratch (device globals: allocation-free per harness rules)
__device__ float g_pred[(size_t)B * P * ND];        // 536 MB
__device__ float g_logits[(size_t)B * P * N];       // 16 MB
__device__ float g_v[(size_t)B * ND];               // 256 KB
__device__ float g_partial[(size_t)B * NCH * ND];   // 8 MB

__device__ __forceinline__ unsigned long long fma_f32x2(
    unsigned long long a, unsigned long long b, unsigned long long c) {
    unsigned long long d;
    asm("fma.rn.f32x2 %0, %1, %2, %3;" : "=l"(d) : "l"(a), "l"(b), "l"(c));
    return d;
}

// ---------------------------------------------------------------------------
// Kernel 1: pred[b,p,n,d] = sum_q w[p,n,d,q] * x[b,p,q]
// One block per p. w_p held in registers (64 floats/thread as packed f32x2),
// reused across all 64 batches. Packed FFMA2 halves fma-pipe pressure.
// ---------------------------------------------------------------------------
__global__ __launch_bounds__(256) void pred_kernel(
    const float* __restrict__ x, const float* __restrict__ w) {
    const int p = blockIdx.x;
    const int t = threadIdx.x;

    // x for all 64 batches at this p, packed as f32x2 pairs: xs[b][j] j=0..7
    __shared__ unsigned long long xs[B][PD / 2];
    for (int e = t; e < B * (PD / 2); e += 256) {
        const int b = e >> 3, j = e & 7;
        xs[b][j] = reinterpret_cast<const unsigned long long*>(
                       x + ((size_t)b * P + p) * PD)[j];
    }

    // w for this thread's 4 outputs (idx = t + 256k), 8 packed pairs each
    unsigned long long wv[4][8];
    const unsigned long long* wp =
        reinterpret_cast<const unsigned long long*>(w + (size_t)p * (ND * PD));
#pragma unroll
    for (int k = 0; k < 4; k++) {
        const int idx = t + 256 * k;
#pragma unroll
        for (int j = 0; j < 8; j++) wv[k][j] = wp[(size_t)idx * 8 + j];
    }
    __syncthreads();

    for (int b = 0; b < B; b++) {
        unsigned long long xb[8];
#pragma unroll
        for (int j = 0; j < 8; j++) xb[j] = xs[b][j];
        float* op = g_pred + ((size_t)b * P + p) * ND + t;
#pragma unroll
        for (int k = 0; k < 4; k++) {
            unsigned long long acc = 0ull;  // packed (0.f, 0.f)
#pragma unroll
            for (int j = 0; j < 8; j++) acc = fma_f32x2(wv[k][j], xb[j], acc);
            float2 f = *reinterpret_cast<float2*>(&acc);
            __stcs(op + 256 * k, f.x + f.y);
        }
    }
}

// ---------------------------------------------------------------------------
// Kernel 2: fused routing pass.
// Block = (chunk, b). For each p in chunk:
//   iter==0: accumulate pred (uniform c = 1/32 applied at end)
//   iter>=1: agreement = <pred, v> over D (warp reduce, lane == d),
//            logits update, softmax over N (warp 0), accumulate c*pred.
// Writes per-(b,chunk) partial s — no atomics.
// Thread mapping: lane = d, n = (t>>5) + 8k for k in 0..3.
// ---------------------------------------------------------------------------
__global__ __launch_bounds__(256) void pass_kernel(int iter) {
    const int chunk = blockIdx.x;
    const int b     = blockIdx.y;
    const int t     = threadIdx.x;
    const int lane  = t & 31;
    const int n0    = t >> 5;

    __shared__ float v_s[ND];
    __shared__ float agg[N];
    __shared__ float c_s[N];

    if (iter > 0) {
        for (int e = t; e < ND; e += 256) v_s[e] = g_v[(size_t)b * ND + e];
    }
    __syncthreads();

    float acc0 = 0.f, acc1 = 0.f, acc2 = 0.f, acc3 = 0.f;
    const int pbase = chunk * CH;

    for (int pi = 0; pi < CH; pi++) {
        const int p = pbase + pi;
        const float* pp = g_pred + ((size_t)b * P + p) * ND;
        const float r0 = __ldcs(pp + t);
        const float r1 = __ldcs(pp + t + 256);
        const float r2 = __ldcs(pp + t + 512);
        const float r3 = __ldcs(pp + t + 768);

        if (iter == 0) {
            acc0 += r0; acc1 += r1; acc2 += r2; acc3 += r3;
        } else {
            float a0 = r0 * v_s[t];
            float a1 = r1 * v_s[t + 256];
            float a2 = r2 * v_s[t + 512];
            float a3 = r3 * v_s[t + 768];
#pragma unroll
            for (int o = 16; o > 0; o >>= 1) {
                a0 += __shfl_xor_sync(0xffffffffu, a0, o);
                a1 += __shfl_xor_sync(0xffffffffu, a1, o);
                a2 += __shfl_xor_sync(0xffffffffu, a2, o);
                a3 += __shfl_xor_sync(0xffffffffu, a3, o);
            }
            if (lane == 0) {
                agg[n0]      = a0;
                agg[n0 + 8]  = a1;
                agg[n0 + 16] = a2;
                agg[n0 + 24] = a3;
            }
            __syncthreads();
            if (t < 32) {
                float lg = agg[t];
                const size_t lidx = ((size_t)b * P + p) * N + t;
                if (iter >= 2) lg += g_logits[lidx];
                if (iter <= 2) g_logits[lidx] = lg;
                // softmax over the 32 n's (warp 0 only, full warp)
                float m = lg;
#pragma unroll
                for (int o = 16; o > 0; o >>= 1)
                    m = fmaxf(m, __shfl_xor_sync(0xffffffffu, m, o));
                const float e = __expf(lg - m);
                float se = e;
#pragma unroll
                for (int o = 16; o > 0; o >>= 1)
                    se += __shfl_xor_sync(0xffffffffu, se, o);
                c_s[t] = e / se;
            }
            __syncthreads();
            acc0 = fmaf(c_s[n0],      r0, acc0);
            acc1 = fmaf(c_s[n0 + 8],  r1, acc1);
            acc2 = fmaf(c_s[n0 + 16], r2, acc2);
            acc3 = fmaf(c_s[n0 + 24], r3, acc3);
        }
    }

    if (iter == 0) {
        const float inv = 1.f / (float)N;
        acc0 *= inv; acc1 *= inv; acc2 *= inv; acc3 *= inv;
    }
    float* op = g_partial + ((size_t)b * NCH + chunk) * ND;
    op[t]       = acc0;
    op[t + 256] = acc1;
    op[t + 512] = acc2;
    op[t + 768] = acc3;
}

// ---------------------------------------------------------------------------
// Kernel 3: reduce partials over chunks, squash over D, write v (or d_out).
// Block per b. Same (lane=d, n=(t>>5)+8k) mapping.
// ---------------------------------------------------------------------------
__global__ __launch_bounds__(256) void reduce_squash_kernel(
    float* __restrict__ out, int is_final) {
    const int b = blockIdx.x;
    const int t = threadIdx.x;

    float s0 = 0.f, s1 = 0.f, s2 = 0.f, s3 = 0.f;
    for (int ch = 0; ch < NCH; ch++) {
        const float* pp = g_partial + ((size_t)b * NCH + ch) * ND;
        s0 += pp[t];
        s1 += pp[t + 256];
        s2 += pp[t + 512];
        s3 += pp[t + 768];
    }

    float q0 = s0 * s0, q1 = s1 * s1, q2 = s2 * s2, q3 = s3 * s3;
#pragma unroll
    for (int o = 16; o > 0; o >>= 1) {
        q0 += __shfl_xor_sync(0xffffffffu, q0, o);
        q1 += __shfl_xor_sync(0xffffffffu, q1, o);
        q2 += __shfl_xor_sync(0xffffffffu, q2, o);
        q3 += __shfl_xor_sync(0xffffffffu, q3, o);
    }
    const float EPS = 1e-7f;
    const float k0 = q0 / ((1.f + q0) * sqrtf(q0 + EPS));
    const float k1 = q1 / ((1.f + q1) * sqrtf(q1 + EPS));
    const float k2 = q2 / ((1.f + q2) * sqrtf(q2 + EPS));
    const float k3 = q3 / ((1.f + q3) * sqrtf(q3 + EPS));

    float* dst = is_final ? (out + (size_t)b * ND) : (g_v + (size_t)b * ND);
    dst[t]       = s0 * k0;
    dst[t + 256] = s1 * k1;
    dst[t + 512] = s2 * k2;
    dst[t + 768] = s3 * k3;
}

// ---------------------------------------------------------------------------
extern "C" void kernel_launch(void* const* d_in, const int* in_sizes, int n_in,
                              void* d_out, int out_size) {
    const float* x = (const float*)d_in[0];
    const float* w = (const float*)d_in[1];
    // Defensive: x has 2,097,152 elems, w has 33,554,432 — swap if reversed.
    if (n_in >= 2 && in_sizes[0] > in_sizes[1]) {
        const float* tmp = x; x = w; w = tmp;
    }
    float* out = (float*)d_out;

    pred_kernel<<<P, 256>>>(x, w);
    for (int it = 0; it < 4; it++) {
        pass_kernel<<<dim3(NCH, B), 256>>>(it);
        reduce_squash_kernel<<<B, 256>>>(out, it == 3 ? 1 : 0);
    }
}

// round 2
// speedup vs baseline: 1.5897x; 1.5897x over previous
#include <cuda_runtime.h>
#include <cuda_fp16.h>
#include <cstdint>
#include <cstddef>

// Problem constants
#define B   64
#define P   2048
#define PD  16
#define N   32
#define D   32
#define ND  1024          // N*D
#define CH  64            // p's per chunk in pass kernel
#define NCH 32            // P / CH
#define NSLOT (NCH * 2)   // partial slots per b (2 p-groups per chunk)

// Scratch (device globals: allocation-free per harness rules)
__device__ __half  g_pred[(size_t)B * P * ND];         // 268 MB (fp16)
__device__ float   g_logits[(size_t)B * P * N];        // 16 MB
__device__ float   g_v[(size_t)B * ND];                // 256 KB
__device__ float   g_partial[(size_t)B * NSLOT * ND];  // 16 MB

__device__ __forceinline__ unsigned long long fma_f32x2(
    unsigned long long a, unsigned long long b, unsigned long long c) {
    unsigned long long d;
    asm("fma.rn.f32x2 %0, %1, %2, %3;" : "=l"(d) : "l"(a), "l"(b), "l"(c));
    return d;
}

// ---------------------------------------------------------------------------
// Kernel 1: pred[b,p,n,d] = sum_q w[p,n,d,q] * x[b,p,q], stored as fp16.
// One block per p. Thread t owns output elements e = 4t..4t+3 so the store
// is one coalesced 8-byte (4x half) write. w_p held in registers, reused
// across all 64 batches. Packed fma.rn.f32x2 halves fma-pipe pressure.
// ---------------------------------------------------------------------------
__global__ __launch_bounds__(256) void pred_kernel(
    const float* __restrict__ x, const float* __restrict__ w) {
    const int p = blockIdx.x;
    const int t = threadIdx.x;

    // x for all 64 batches at this p, packed as f32x2 pairs
    __shared__ unsigned long long xs[B][PD / 2];
    for (int e = t; e < B * (PD / 2); e += 256) {
        const int b = e >> 3, j = e & 7;
        xs[b][j] = reinterpret_cast<const unsigned long long*>(
                       x + ((size_t)b * P + p) * PD)[j];
    }

    // w rows for this thread's 4 outputs (e = 4t+j), 8 packed pairs each
    unsigned long long wv[4][8];
    const unsigned long long* wp =
        reinterpret_cast<const unsigned long long*>(w + (size_t)p * (ND * PD));
#pragma unroll
    for (int j = 0; j < 4; j++) {
        const int row = 4 * t + j;
#pragma unroll
        for (int k = 0; k < 8; k++) wv[j][k] = wp[(size_t)row * 8 + k];
    }
    __syncthreads();

    for (int b = 0; b < B; b++) {
        unsigned long long xb[8];
#pragma unroll
        for (int k = 0; k < 8; k++) xb[k] = xs[b][k];
        float r[4];
#pragma unroll
        for (int j = 0; j < 4; j++) {
            unsigned long long acc = 0ull;
#pragma unroll
            for (int k = 0; k < 8; k++) acc = fma_f32x2(wv[j][k], xb[k], acc);
            float2 f = *reinterpret_cast<float2*>(&acc);
            r[j] = f.x + f.y;
        }
        __half2 h0 = __floats2half2_rn(r[0], r[1]);
        __half2 h1 = __floats2half2_rn(r[2], r[3]);
        uint2 pk;
        pk.x = *reinterpret_cast<unsigned*>(&h0);
        pk.y = *reinterpret_cast<unsigned*>(&h1);
        uint2* op = reinterpret_cast<uint2*>(
            g_pred + ((size_t)b * P + p) * ND) + t;
        __stcs(reinterpret_cast<float2*>(op), *reinterpret_cast<float2*>(&pk));
    }
}

// ---------------------------------------------------------------------------
// Kernel 2: fused routing pass over a chunk of CH p's for one b.
// 2 p's per iteration: warps 0-3 own p0 (g=0), warps 4-7 own p1 (g=1).
// Thread (g, u=t&127) loads one uint4 = 8 halfs = elements e=8u..8u+7 of
// pred[b, p+g, :]; n = u>>2. Agreement reduced with 2 shuffles (lanes t&3).
// Next tile is prefetched before the barrier chain of the current tile.
// ---------------------------------------------------------------------------
__global__ __launch_bounds__(256) void pass_kernel(int iter) {
    const int chunk = blockIdx.x;
    const int b     = blockIdx.y;
    const int t     = threadIdx.x;
    const int g     = t >> 7;        // which p of the pair
    const int u     = t & 127;       // row within p (8 elements each)
    const int n     = u >> 2;        // capsule index for this thread

    __shared__ float v_s[ND];
    __shared__ float agg[2][N];
    __shared__ float c_s[2][N];

    if (iter > 0) {
        for (int e = t; e < ND; e += 256) v_s[e] = g_v[(size_t)b * ND + e];
        __syncthreads();
    }

    float acc[8];
#pragma unroll
    for (int k = 0; k < 8; k++) acc[k] = 0.f;

    const uint4* base = reinterpret_cast<const uint4*>(
        g_pred + ((size_t)b * P + (size_t)chunk * CH) * ND);

    uint4 cur = __ldcs(base + (size_t)g * 128 + u);

    for (int pi = 0; pi < CH; pi += 2) {
        const int pn = (pi + 2 < CH) ? pi + 2 : pi;      // clamp: harmless reload
        uint4 nxt = __ldcs(base + (size_t)(pn + g) * 128 + u);

        // unpack 8 halfs -> 8 floats
        float f[8];
        {
            const __half2* h = reinterpret_cast<const __half2*>(&cur);
#pragma unroll
            for (int k = 0; k < 4; k++) {
                float2 fl = __half22float2(h[k]);
                f[2 * k] = fl.x; f[2 * k + 1] = fl.y;
            }
        }

        if (iter == 0) {
#pragma unroll
            for (int k = 0; k < 8; k++) acc[k] += f[k];
        } else {
            const int e0 = 8 * u;
            float a = 0.f;
#pragma unroll
            for (int k = 0; k < 8; k++) a = fmaf(f[k], v_s[e0 + k], a);
            a += __shfl_xor_sync(0xffffffffu, a, 1);
            a += __shfl_xor_sync(0xffffffffu, a, 2);
            if ((t & 3) == 0) agg[g][n] = a;
            __syncthreads();

            // softmax over N: warp 0 handles g=0, warp 4 handles g=1
            if ((t & 127) < 32) {
                const int gg = t >> 7;
                const int nn = t & 31;
                const int p  = chunk * CH + pi + gg;
                float lg = agg[gg][nn];
                const size_t lidx = ((size_t)b * P + p) * N + nn;
                if (iter >= 2) lg += g_logits[lidx];
                if (iter <= 2) g_logits[lidx] = lg;
                float m = lg;
#pragma unroll
                for (int o = 16; o > 0; o >>= 1)
                    m = fmaxf(m, __shfl_xor_sync(0xffffffffu, m, o));
                const float ex = __expf(lg - m);
                float se = ex;
#pragma unroll
                for (int o = 16; o > 0; o >>= 1)
                    se += __shfl_xor_sync(0xffffffffu, se, o);
                c_s[gg][nn] = ex / se;
            }
            __syncthreads();

            const float c = c_s[g][n];
#pragma unroll
            for (int k = 0; k < 8; k++) acc[k] = fmaf(c, f[k], acc[k]);
        }
        cur = nxt;
    }

    if (iter == 0) {
        const float inv = 1.f / (float)N;
#pragma unroll
        for (int k = 0; k < 8; k++) acc[k] *= inv;
    }

    // per-(b, chunk, g) partial; elements e = 8u..8u+7
    float* op = g_partial +
        ((size_t)b * NSLOT + (size_t)chunk * 2 + g) * ND + 8 * u;
    float4 o0 = make_float4(acc[0], acc[1], acc[2], acc[3]);
    float4 o1 = make_float4(acc[4], acc[5], acc[6], acc[7]);
    *reinterpret_cast<float4*>(op)     = o0;
    *reinterpret_cast<float4*>(op + 4) = o1;
}

// ---------------------------------------------------------------------------
// Kernel 3: reduce partials over slots, squash over D, write v (or d_out).
// Block per b. lane = d, n = (t>>5) + 8k.
// ---------------------------------------------------------------------------
__global__ __launch_bounds__(256) void reduce_squash_kernel(
    float* __restrict__ out, int is_final) {
    const int b = blockIdx.x;
    const int t = threadIdx.x;

    float s0 = 0.f, s1 = 0.f, s2 = 0.f, s3 = 0.f;
    for (int ch = 0; ch < NSLOT; ch++) {
        const float* pp = g_partial + ((size_t)b * NSLOT + ch) * ND;
        s0 += pp[t];
        s1 += pp[t + 256];
        s2 += pp[t + 512];
        s3 += pp[t + 768];
    }

    float q0 = s0 * s0, q1 = s1 * s1, q2 = s2 * s2, q3 = s3 * s3;
#pragma unroll
    for (int o = 16; o > 0; o >>= 1) {
        q0 += __shfl_xor_sync(0xffffffffu, q0, o);
        q1 += __shfl_xor_sync(0xffffffffu, q1, o);
        q2 += __shfl_xor_sync(0xffffffffu, q2, o);
        q3 += __shfl_xor_sync(0xffffffffu, q3, o);
    }
    const float EPS = 1e-7f;
    const float k0 = q0 / ((1.f + q0) * sqrtf(q0 + EPS));
    const float k1 = q1 / ((1.f + q1) * sqrtf(q1 + EPS));
    const float k2 = q2 / ((1.f + q2) * sqrtf(q2 + EPS));
    const float k3 = q3 / ((1.f + q3) * sqrtf(q3 + EPS));

    float* dst = is_final ? (out + (size_t)b * ND) : (g_v + (size_t)b * ND);
    dst[t]       = s0 * k0;
    dst[t + 256] = s1 * k1;
    dst[t + 512] = s2 * k2;
    dst[t + 768] = s3 * k3;
}

// ---------------------------------------------------------------------------
extern "C" void kernel_launch(void* const* d_in, const int* in_sizes, int n_in,
                              void* d_out, int out_size) {
    const float* x = (const float*)d_in[0];
    const float* w = (const float*)d_in[1];
    if (n_in >= 2 && in_sizes[0] > in_sizes[1]) {
        const float* tmp = x; x = w; w = tmp;
    }
    float* out = (float*)d_out;

    pred_kernel<<<P, 256>>>(x, w);
    for (int it = 0; it < 4; it++) {
        pass_kernel<<<dim3(NCH, B), 256>>>(it);
        reduce_squash_kernel<<<B, 256>>>(out, it == 3 ? 1 : 0);
    }
}

// round 3
// speedup vs baseline: 1.9086x; 1.2007x over previous
#include <cuda_runtime.h>
#include <cuda_fp16.h>
#include <cstdint>
#include <cstddef>

// Problem constants
#define B   64
#define P   2048
#define PD  16
#define N   32
#define D   32
#define ND  1024          // N*D
#define CH  64            // p's per chunk in pass kernel
#define NCH 32            // P / CH

// Scratch (device globals: allocation-free per harness rules)
__device__ __half  g_pred[(size_t)B * P * ND];        // 268 MB (fp16)
__device__ float   g_logits[(size_t)B * P * N];       // 16 MB
__device__ float   g_v[(size_t)B * ND];               // 256 KB
__device__ float   g_partial[(size_t)B * NCH * ND];   // 8 MB

__device__ __forceinline__ unsigned long long fma_f32x2(
    unsigned long long a, unsigned long long b, unsigned long long c) {
    unsigned long long d;
    asm("fma.rn.f32x2 %0, %1, %2, %3;" : "=l"(d) : "l"(a), "l"(b), "l"(c));
    return d;
}

__device__ __forceinline__ void unpack8(const uint4& u, float* f) {
    const __half2* h = reinterpret_cast<const __half2*>(&u);
#pragma unroll
    for (int k = 0; k < 4; k++) {
        float2 t = __half22float2(h[k]);
        f[2 * k] = t.x; f[2 * k + 1] = t.y;
    }
}

// ---------------------------------------------------------------------------
// Kernel 1: pred[b,p,n,d] = sum_q w[p,n,d,q] * x[b,p,q], stored fp16.
// 2 blocks per p (each covers 512 of the 1024 outputs); 2 outputs/thread so
// w stays in ~32 registers -> 4 blocks/SM instead of 1. Stores half2.
// ---------------------------------------------------------------------------
__global__ __launch_bounds__(256) void pred_kernel(
    const float* __restrict__ x, const float* __restrict__ w) {
    const int p    = blockIdx.x >> 1;
    const int half = blockIdx.x & 1;
    const int t    = threadIdx.x;
    const int e0   = half * 512 + 2 * t;   // first of 2 consecutive outputs

    __shared__ unsigned long long xs[B][PD / 2];
    for (int e = t; e < B * (PD / 2); e += 256) {
        const int b = e >> 3, j = e & 7;
        xs[b][j] = reinterpret_cast<const unsigned long long*>(
                       x + ((size_t)b * P + p) * PD)[j];
    }

    unsigned long long wv[2][8];
    const unsigned long long* wp =
        reinterpret_cast<const unsigned long long*>(w + (size_t)p * (ND * PD));
#pragma unroll
    for (int j = 0; j < 2; j++)
#pragma unroll
        for (int k = 0; k < 8; k++)
            wv[j][k] = wp[(size_t)(e0 + j) * 8 + k];
    __syncthreads();

    for (int b = 0; b < B; b++) {
        unsigned long long xb[8];
#pragma unroll
        for (int k = 0; k < 8; k++) xb[k] = xs[b][k];
        float r[2];
#pragma unroll
        for (int j = 0; j < 2; j++) {
            unsigned long long acc = 0ull;
#pragma unroll
            for (int k = 0; k < 8; k++) acc = fma_f32x2(wv[j][k], xb[k], acc);
            float2 f = *reinterpret_cast<float2*>(&acc);
            r[j] = f.x + f.y;
        }
        __half2 h = __floats2half2_rn(r[0], r[1]);
        float* op = reinterpret_cast<float*>(
            g_pred + ((size_t)b * P + p) * ND + e0);
        __stcs(op, __uint_as_float(*reinterpret_cast<unsigned*>(&h)));
    }
}

// ---------------------------------------------------------------------------
// Kernel 2: fused routing pass, warp-per-p, barrier-free main loop.
// Block = (chunk, b), 8 warps; warp w owns p = chunk*64 + w*8 + i, i=0..7.
// Lane n loads pred[p][n][0..31] (4x LDG.128 halfs). Agreement is a fully
// lane-local dot product with v[n][:] (held in 32 regs). Softmax over N is a
// 5-shuffle intra-warp sum (no max subtraction: |logit| <= ~8 by
// Cauchy-Schwarz, exp safe in fp32). acc[32] per lane. Next p prefetched.
// One __syncthreads at the end for the cross-warp reduction into g_partial.
// ---------------------------------------------------------------------------
__global__ __launch_bounds__(256, 2) void pass_kernel(int iter) {
    const int chunk = blockIdx.x;
    const int b     = blockIdx.y;
    const int t     = threadIdx.x;
    const int w     = t >> 5;
    const int lane  = t & 31;
    const int p0    = chunk * CH + w * 8;

    __shared__ float wsum[8][N * 33];   // padded: elem (n,d) at n*33+d

    float v[32];
    if (iter > 0) {
        const float4* vp = reinterpret_cast<const float4*>(
            g_v + (size_t)b * ND + (size_t)lane * 32);
#pragma unroll
        for (int j = 0; j < 8; j++) {
            float4 q = vp[j];
            v[4 * j] = q.x; v[4 * j + 1] = q.y;
            v[4 * j + 2] = q.z; v[4 * j + 3] = q.w;
        }
    }

    float acc[32];
#pragma unroll
    for (int k = 0; k < 32; k++) acc[k] = 0.f;

    const uint4* base = reinterpret_cast<const uint4*>(
        g_pred + ((size_t)b * P + p0) * ND) + lane * 4;
    float* lgp = g_logits + ((size_t)b * P + p0) * N + lane;

    uint4 c0 = __ldcs(base + 0), c1 = __ldcs(base + 1);
    uint4 c2 = __ldcs(base + 2), c3 = __ldcs(base + 3);

    for (int i = 0; i < 8; i++) {
        const uint4* nb = base + (size_t)((i + 1 < 8) ? (i + 1) : i) * 128;
        uint4 n0 = __ldcs(nb + 0), n1 = __ldcs(nb + 1);
        uint4 n2 = __ldcs(nb + 2), n3 = __ldcs(nb + 3);

        float f[8];
        if (iter == 0) {
            unpack8(c0, f);
#pragma unroll
            for (int k = 0; k < 8; k++) acc[k] += f[k];
            unpack8(c1, f);
#pragma unroll
            for (int k = 0; k < 8; k++) acc[8 + k] += f[k];
            unpack8(c2, f);
#pragma unroll
            for (int k = 0; k < 8; k++) acc[16 + k] += f[k];
            unpack8(c3, f);
#pragma unroll
            for (int k = 0; k < 8; k++) acc[24 + k] += f[k];
        } else {
            float a0 = 0.f, a1 = 0.f, a2 = 0.f, a3 = 0.f;
            unpack8(c0, f);
#pragma unroll
            for (int k = 0; k < 8; k++) a0 = fmaf(f[k], v[k], a0);
            unpack8(c1, f);
#pragma unroll
            for (int k = 0; k < 8; k++) a1 = fmaf(f[k], v[8 + k], a1);
            unpack8(c2, f);
#pragma unroll
            for (int k = 0; k < 8; k++) a2 = fmaf(f[k], v[16 + k], a2);
            unpack8(c3, f);
#pragma unroll
            for (int k = 0; k < 8; k++) a3 = fmaf(f[k], v[24 + k], a3);

            float lg = (a0 + a1) + (a2 + a3);
            if (iter >= 2) lg += lgp[(size_t)i * N];
            if (iter <= 2) lgp[(size_t)i * N] = lg;

            const float ex = __expf(lg);
            float se = ex;
#pragma unroll
            for (int o = 16; o > 0; o >>= 1)
                se += __shfl_xor_sync(0xffffffffu, se, o);
            const float c = __fdividef(ex, se);

            unpack8(c0, f);
#pragma unroll
            for (int k = 0; k < 8; k++) acc[k] = fmaf(c, f[k], acc[k]);
            unpack8(c1, f);
#pragma unroll
            for (int k = 0; k < 8; k++) acc[8 + k] = fmaf(c, f[k], acc[8 + k]);
            unpack8(c2, f);
#pragma unroll
            for (int k = 0; k < 8; k++) acc[16 + k] = fmaf(c, f[k], acc[16 + k]);
            unpack8(c3, f);
#pragma unroll
            for (int k = 0; k < 8; k++) acc[24 + k] = fmaf(c, f[k], acc[24 + k]);
        }
        c0 = n0; c1 = n1; c2 = n2; c3 = n3;
    }

    // cross-warp reduction (padded layout: conflict-free scalar STS/LDS)
    const float scale = (iter == 0) ? (1.f / (float)N) : 1.f;
    float* ws = &wsum[w][lane * 33];
#pragma unroll
    for (int k = 0; k < 32; k++) ws[k] = acc[k] * scale;
    __syncthreads();

    float* op = g_partial + ((size_t)b * NCH + chunk) * ND;
#pragma unroll
    for (int j = 0; j < 4; j++) {
        const int e = t + 256 * j;
        const int n = e >> 5, d = e & 31;
        float s = 0.f;
#pragma unroll
        for (int ww = 0; ww < 8; ww++) s += wsum[ww][n * 33 + d];
        op[e] = s;
    }
}

// ---------------------------------------------------------------------------
// Kernel 3: reduce partials over chunks, squash over D, write v (or d_out).
// Block per b. lane = d, n = (t>>5) + 8k.
// ---------------------------------------------------------------------------
__global__ __launch_bounds__(256) void reduce_squash_kernel(
    float* __restrict__ out, int is_final) {
    const int b = blockIdx.x;
    const int t = threadIdx.x;

    float s0 = 0.f, s1 = 0.f, s2 = 0.f, s3 = 0.f;
    for (int ch = 0; ch < NCH; ch++) {
        const float* pp = g_partial + ((size_t)b * NCH + ch) * ND;
        s0 += pp[t];
        s1 += pp[t + 256];
        s2 += pp[t + 512];
        s3 += pp[t + 768];
    }

    float q0 = s0 * s0, q1 = s1 * s1, q2 = s2 * s2, q3 = s3 * s3;
#pragma unroll
    for (int o = 16; o > 0; o >>= 1) {
        q0 += __shfl_xor_sync(0xffffffffu, q0, o);
        q1 += __shfl_xor_sync(0xffffffffu, q1, o);
        q2 += __shfl_xor_sync(0xffffffffu, q2, o);
        q3 += __shfl_xor_sync(0xffffffffu, q3, o);
    }
    const float EPS = 1e-7f;
    const float k0 = q0 / ((1.f + q0) * sqrtf(q0 + EPS));
    const float k1 = q1 / ((1.f + q1) * sqrtf(q1 + EPS));
    const float k2 = q2 / ((1.f + q2) * sqrtf(q2 + EPS));
    const float k3 = q3 / ((1.f + q3) * sqrtf(q3 + EPS));

    float* dst = is_final ? (out + (size_t)b * ND) : (g_v + (size_t)b * ND);
    dst[t]       = s0 * k0;
    dst[t + 256] = s1 * k1;
    dst[t + 512] = s2 * k2;
    dst[t + 768] = s3 * k3;
}

// ---------------------------------------------------------------------------
extern "C" void kernel_launch(void* const* d_in, const int* in_sizes, int n_in,
                              void* d_out, int out_size) {
    const float* x = (const float*)d_in[0];
    const float* w = (const float*)d_in[1];
    if (n_in >= 2 && in_sizes[0] > in_sizes[1]) {
        const float* tmp = x; x = w; w = tmp;
    }
    float* out = (float*)d_out;

    pred_kernel<<<2 * P, 256>>>(x, w);
    for (int it = 0; it < 4; it++) {
        pass_kernel<<<dim3(NCH, B), 256>>>(it);
        reduce_squash_kernel<<<B, 256>>>(out, it == 3 ? 1 : 0);
    }
}

// round 4
// speedup vs baseline: 2.0106x; 1.0534x over previous
#include <cuda_runtime.h>
#include <cuda_fp16.h>
#include <cstdint>
#include <cstddef>

// Problem constants
#define B   64
#define P   2048
#define PD  16
#define N   32
#define D   32
#define ND  1024          // N*D
#define CH  64            // p's per chunk in pass kernel
#define NCH 32            // P / CH
#define ROWB 2048         // bytes per p-row of pred (1024 halfs)
#define STAGE_P 16
#define STAGE_BYTES (STAGE_P * ROWB)   // 32768

// Scratch (device globals: allocation-free per harness rules)
__device__ __half  g_pred[(size_t)B * P * ND];        // 268 MB (fp16, swizzled rows)
__device__ float   g_logits[(size_t)B * P * N];       // 16 MB
__device__ float   g_v[(size_t)B * ND];               // 256 KB
__device__ float   g_partial[(size_t)B * NCH * ND];   // 8 MB

__device__ __forceinline__ unsigned long long fma_f32x2(
    unsigned long long a, unsigned long long b, unsigned long long c) {
    unsigned long long d;
    asm("fma.rn.f32x2 %0, %1, %2, %3;" : "=l"(d) : "l"(a), "l"(b), "l"(c));
    return d;
}

__device__ __forceinline__ uint32_t smem_u32(const void* p) {
    uint32_t a;
    asm("{ .reg .u64 t; cvta.to.shared.u64 t, %1; cvt.u32.u64 %0, t; }"
        : "=r"(a) : "l"(p));
    return a;
}

__device__ __forceinline__ void mbar_init(uint32_t mbar, uint32_t cnt) {
    asm volatile("mbarrier.init.shared.b64 [%0], %1;" :: "r"(mbar), "r"(cnt)
                 : "memory");
}
__device__ __forceinline__ void mbar_expect_tx(uint32_t mbar, uint32_t bytes) {
    asm volatile("mbarrier.arrive.expect_tx.shared.b64 _, [%0], %1;"
                 :: "r"(mbar), "r"(bytes) : "memory");
}
__device__ __forceinline__ void mbar_wait(uint32_t mbar, uint32_t parity) {
    asm volatile(
        "{\n\t"
        ".reg .pred P1;\n\t"
        "WAIT_LOOP_%=:\n\t"
        "mbarrier.try_wait.parity.acquire.cta.shared::cta.b64 P1, [%0], %1, 0x989680;\n\t"
        "@P1 bra.uni WAIT_DONE_%=;\n\t"
        "bra.uni WAIT_LOOP_%=;\n\t"
        "WAIT_DONE_%=:\n\t"
        "}"
        :: "r"(mbar), "r"(parity) : "memory");
}
__device__ __forceinline__ void bulk_g2s(uint32_t dst, const void* src,
                                         uint32_t bytes, uint32_t mbar) {
    asm volatile(
        "cp.async.bulk.shared::cluster.global.mbarrier::complete_tx::bytes "
        "[%0], [%1], %2, [%3];"
        :: "r"(dst), "l"(src), "r"(bytes), "r"(mbar) : "memory");
}

__device__ __forceinline__ void unpack8(const uint4& u, float* f) {
    const __half2* h = reinterpret_cast<const __half2*>(&u);
#pragma unroll
    for (int k = 0; k < 4; k++) {
        float2 t = __half22float2(h[k]);
        f[2 * k] = t.x; f[2 * k + 1] = t.y;
    }
}

// ---------------------------------------------------------------------------
// Kernel 1: pred[b,p,n,d] = sum_q w[p,n,d,q] * x[b,p,q], stored fp16 with a
// 16B-chunk swizzle inside each p-row: chunk k of capsule n lands at slot
// (k + ((n>>1)&3)) & 3. Keeps global stores coalesced (permutation within
// 128B lines) and makes the pass kernel's smem reads bank-conflict-free.
// ---------------------------------------------------------------------------
__global__ __launch_bounds__(256) void pred_kernel(
    const float* __restrict__ x, const float* __restrict__ w) {
    const int p    = blockIdx.x >> 1;
    const int half = blockIdx.x & 1;
    const int t    = threadIdx.x;
    const int e0   = half * 512 + 2 * t;   // first of 2 consecutive outputs

    __shared__ uint4 xs4[B][PD / 4];
    for (int e = t; e < B * (PD / 4); e += 256) {
        const int b = e >> 2, j = e & 3;
        xs4[b][j] = reinterpret_cast<const uint4*>(
                        x + ((size_t)b * P + p) * PD)[j];
    }

    unsigned long long wv[2][8];
    const unsigned long long* wp =
        reinterpret_cast<const unsigned long long*>(w + (size_t)p * (ND * PD));
#pragma unroll
    for (int j = 0; j < 2; j++)
#pragma unroll
        for (int k = 0; k < 8; k++)
            wv[j][k] = wp[(size_t)(e0 + j) * 8 + k];
    __syncthreads();

    // swizzled destination offset within the p-row (constant per thread)
    const int n    = e0 >> 5;
    const int kk   = (e0 >> 3) & 3;
    const int slot = (kk + ((n >> 1) & 3)) & 3;
    const int off  = n * 64 + slot * 16 + (e0 & 7) * 2;

    for (int b = 0; b < B; b++) {
        unsigned long long xb[8];
#pragma unroll
        for (int j = 0; j < 4; j++) {
            uint4 q = xs4[b][j];
            xb[2 * j]     = *reinterpret_cast<unsigned long long*>(&q.x);
            xb[2 * j + 1] = *reinterpret_cast<unsigned long long*>(&q.z);
        }
        float r[2];
#pragma unroll
        for (int j = 0; j < 2; j++) {
            unsigned long long acc = 0ull;
#pragma unroll
            for (int k = 0; k < 8; k++) acc = fma_f32x2(wv[j][k], xb[k], acc);
            float2 f = *reinterpret_cast<float2*>(&acc);
            r[j] = f.x + f.y;
        }
        __half2 h = __floats2half2_rn(r[0], r[1]);
        char* dst = reinterpret_cast<char*>(g_pred) +
                    ((size_t)b * P + p) * ROWB + off;
        __stcs(reinterpret_cast<float*>(dst),
               __uint_as_float(*reinterpret_cast<unsigned*>(&h)));
    }
}

// ---------------------------------------------------------------------------
// Kernel 2: fused routing pass. Block = (chunk, b). The 64-p chunk streams
// through smem in four 32KB stages via cp.async.bulk (2 buffers, mbarriers),
// so DRAM MLP is provided by the copy engine, not per-warp LDGs.
// Warp w handles p_local = s*16 + w*2 + {0,1}. Lane n reads its capsule's
// 64B (4x LDS.128, swizzle-rotated slots -> conflict-free), computes the
// lane-local agreement dot with v[n][:] (regs), intra-warp softmax over N,
// and accumulates c*pred into acc[32].
// ---------------------------------------------------------------------------
extern __shared__ char dsm[];
__global__ __launch_bounds__(256, 2) void pass_kernel(int iter) {
    const int chunk = blockIdx.x;
    const int b     = blockIdx.y;
    const int t     = threadIdx.x;
    const int w     = t >> 5;
    const int lane  = t & 31;
    const int rot   = (lane >> 1) & 3;

    const uint32_t smem_base = smem_u32(dsm);
    const uint32_t mbar0 = smem_base + 2 * STAGE_BYTES;
    const uint32_t mbar1 = mbar0 + 8;

    if (t == 0) { mbar_init(mbar0, 1); mbar_init(mbar1, 1); }
    __syncthreads();

    const char* gsrc = reinterpret_cast<const char*>(g_pred) +
                       ((size_t)b * P + (size_t)chunk * CH) * ROWB;
    if (t == 0) {
        mbar_expect_tx(mbar0, STAGE_BYTES);
        bulk_g2s(smem_base, gsrc, STAGE_BYTES, mbar0);
        mbar_expect_tx(mbar1, STAGE_BYTES);
        bulk_g2s(smem_base + STAGE_BYTES, gsrc + STAGE_BYTES, STAGE_BYTES, mbar1);
    }

    float v[32];
    if (iter > 0) {
        const float4* vp = reinterpret_cast<const float4*>(
            g_v + (size_t)b * ND + (size_t)lane * 32);
#pragma unroll
        for (int j = 0; j < 8; j++) {
            float4 q = vp[j];
            v[4 * j] = q.x; v[4 * j + 1] = q.y;
            v[4 * j + 2] = q.z; v[4 * j + 3] = q.w;
        }
    }

    float acc[32];
#pragma unroll
    for (int k = 0; k < 32; k++) acc[k] = 0.f;

    float* lgbase = g_logits + ((size_t)b * P + (size_t)chunk * CH) * N + lane;

    for (int s = 0; s < 4; s++) {
        mbar_wait((s & 1) ? mbar1 : mbar0, s >> 1);
        const char* buf = dsm + (s & 1) * STAGE_BYTES;

#pragma unroll
        for (int j = 0; j < 2; j++) {
            const int pl = s * STAGE_P + w * 2 + j;   // p within chunk
            const char* row = buf + (w * 2 + j) * ROWB;

            uint4 q[4];
#pragma unroll
            for (int k = 0; k < 4; k++) {
                const int slot = (k + rot) & 3;
                q[k] = *reinterpret_cast<const uint4*>(row + lane * 64 + slot * 16);
            }

            float f[8];
            if (iter == 0) {
#pragma unroll
                for (int c = 0; c < 4; c++) {
                    unpack8(q[c], f);
#pragma unroll
                    for (int k = 0; k < 8; k++) acc[8 * c + k] += f[k];
                }
            } else {
                float a0 = 0.f, a1 = 0.f, a2 = 0.f, a3 = 0.f;
                float fl[32];
#pragma unroll
                for (int c = 0; c < 4; c++) unpack8(q[c], fl + 8 * c);
#pragma unroll
                for (int k = 0; k < 8; k++) {
                    a0 = fmaf(fl[k],      v[k],      a0);
                    a1 = fmaf(fl[8 + k],  v[8 + k],  a1);
                    a2 = fmaf(fl[16 + k], v[16 + k], a2);
                    a3 = fmaf(fl[24 + k], v[24 + k], a3);
                }
                float lg = (a0 + a1) + (a2 + a3);
                float* lgp = lgbase + (size_t)pl * N;
                if (iter >= 2) lg += *lgp;
                if (iter <= 2) *lgp = lg;

                const float ex = __expf(lg);
                float se = ex;
#pragma unroll
                for (int o = 16; o > 0; o >>= 1)
                    se += __shfl_xor_sync(0xffffffffu, se, o);
                const float c = __fdividef(ex, se);
#pragma unroll
                for (int k = 0; k < 32; k++) acc[k] = fmaf(c, fl[k], acc[k]);
            }
        }
        __syncthreads();
        if (t == 0 && s < 2) {
            const uint32_t mb = (s & 1) ? mbar1 : mbar0;
            mbar_expect_tx(mb, STAGE_BYTES);
            bulk_g2s(smem_base + (s & 1) * STAGE_BYTES,
                     gsrc + (size_t)(s + 2) * STAGE_BYTES, STAGE_BYTES, mb);
        }
    }

    // cross-warp reduction; wsum overlaps the (now idle) stage buffers.
    // layout: wsum[w][d][n] at float index w*1056 + d*33 + n (conflict-free)
    float* wsum = reinterpret_cast<float*>(dsm);
    const float scale = (iter == 0) ? (1.f / (float)N) : 1.f;
    __syncthreads();   // everyone done reading buf1 before overwrite
    float* ws = wsum + w * 1056 + lane;
#pragma unroll
    for (int d = 0; d < 32; d++) ws[d * 33] = acc[d] * scale;
    __syncthreads();

    float* op = g_partial + ((size_t)b * NCH + chunk) * ND;
#pragma unroll
    for (int jj = 0; jj < 4; jj++) {
        const int e = t + 256 * jj;
        const int n = e >> 5, d = e & 31;
        float sv = 0.f;
#pragma unroll
        for (int ww = 0; ww < 8; ww++) sv += wsum[ww * 1056 + d * 33 + n];
        op[e] = sv;
    }
}

// ---------------------------------------------------------------------------
// Kernel 3: reduce partials over chunks, squash over D, write v (or d_out).
// Grid (B, 4): block (b,g) handles 256 elements e = g*256 + t.
// ---------------------------------------------------------------------------
__global__ __launch_bounds__(256) void reduce_squash_kernel(
    float* __restrict__ out, int is_final) {
    const int b = blockIdx.x;
    const int g = blockIdx.y;
    const int t = threadIdx.x;
    const int e = g * 256 + t;

    float s = 0.f;
    const float* pp = g_partial + (size_t)b * NCH * ND + e;
#pragma unroll
    for (int ch = 0; ch < NCH; ch++) s += pp[(size_t)ch * ND];

    float q = s * s;
#pragma unroll
    for (int o = 16; o > 0; o >>= 1)
        q += __shfl_xor_sync(0xffffffffu, q, o);
    const float EPS = 1e-7f;
    const float k = q / ((1.f + q) * sqrtf(q + EPS));

    float* dst = is_final ? (out + (size_t)b * ND) : (g_v + (size_t)b * ND);
    dst[e] = s * k;
}

// ---------------------------------------------------------------------------
extern "C" void kernel_launch(void* const* d_in, const int* in_sizes, int n_in,
                              void* d_out, int out_size) {
    const float* x = (const float*)d_in[0];
    const float* w = (const float*)d_in[1];
    if (n_in >= 2 && in_sizes[0] > in_sizes[1]) {
        const float* tmp = x; x = w; w = tmp;
    }
    float* out = (float*)d_out;

    const int dyn = 2 * STAGE_BYTES + 32;   // bufs + mbarriers
    cudaFuncSetAttribute(pass_kernel,
                         cudaFuncAttributeMaxDynamicSharedMemorySize, dyn);

    pred_kernel<<<2 * P, 256>>>(x, w);
    for (int it = 0; it < 4; it++) {
        pass_kernel<<<dim3(NCH, B), 256, dyn>>>(it);
        reduce_squash_kernel<<<dim3(B, 4), 256>>>(out, it == 3 ? 1 : 0);
    }
}

// round 5
// speedup vs baseline: 2.0772x; 1.0331x over previous
#include <cuda_runtime.h>
#include <cuda_fp16.h>
#include <cstdint>
#include <cstddef>

// Problem constants
#define B   64
#define P   2048
#define PD  16
#define N   32
#define D   32
#define ND  1024          // N*D
#define CH  64            // p's per chunk in pass kernel
#define NCH 32            // P / CH
#define ROWB 2048         // bytes per p-row of pred (1024 halfs)
#define STAGE_P 16
#define STAGE_BYTES (STAGE_P * ROWB)   // 32768
#define NBUF 3
#define NSTAGE 4          // CH / STAGE_P

// Scratch (device globals: allocation-free per harness rules)
__device__ __half  g_pred[(size_t)B * P * ND];        // 268 MB (fp16, swizzled rows)
__device__ float   g_logits[(size_t)B * P * N];       // 16 MB
__device__ float   g_v[(size_t)B * ND];               // 256 KB
__device__ float   g_partial[(size_t)B * NCH * ND];   // 8 MB

__device__ __forceinline__ unsigned long long fma_f32x2(
    unsigned long long a, unsigned long long b, unsigned long long c) {
    unsigned long long d;
    asm("fma.rn.f32x2 %0, %1, %2, %3;" : "=l"(d) : "l"(a), "l"(b), "l"(c));
    return d;
}

__device__ __forceinline__ uint32_t smem_u32(const void* p) {
    uint32_t a;
    asm("{ .reg .u64 t; cvta.to.shared.u64 t, %1; cvt.u32.u64 %0, t; }"
        : "=r"(a) : "l"(p));
    return a;
}

__device__ __forceinline__ void mbar_init(uint32_t mbar, uint32_t cnt) {
    asm volatile("mbarrier.init.shared.b64 [%0], %1;" :: "r"(mbar), "r"(cnt)
                 : "memory");
}
__device__ __forceinline__ void mbar_expect_tx(uint32_t mbar, uint32_t bytes) {
    asm volatile("mbarrier.arrive.expect_tx.shared.b64 _, [%0], %1;"
                 :: "r"(mbar), "r"(bytes) : "memory");
}
__device__ __forceinline__ void mbar_wait(uint32_t mbar, uint32_t parity) {
    asm volatile(
        "{\n\t"
        ".reg .pred P1;\n\t"
        "WAIT_LOOP_%=:\n\t"
        "mbarrier.try_wait.parity.acquire.cta.shared::cta.b64 P1, [%0], %1, 0x989680;\n\t"
        "@P1 bra.uni WAIT_DONE_%=;\n\t"
        "bra.uni WAIT_LOOP_%=;\n\t"
        "WAIT_DONE_%=:\n\t"
        "}"
        :: "r"(mbar), "r"(parity) : "memory");
}
__device__ __forceinline__ void bulk_g2s(uint32_t dst, const void* src,
                                         uint32_t bytes, uint32_t mbar) {
    asm volatile(
        "cp.async.bulk.shared::cluster.global.mbarrier::complete_tx::bytes "
        "[%0], [%1], %2, [%3];"
        :: "r"(dst), "l"(src), "r"(bytes), "r"(mbar) : "memory");
}

__device__ __forceinline__ void unpack8(const uint4& u, float* f) {
    const __half2* h = reinterpret_cast<const __half2*>(&u);
#pragma unroll
    for (int k = 0; k < 4; k++) {
        float2 t = __half22float2(h[k]);
        f[2 * k] = t.x; f[2 * k + 1] = t.y;
    }
}

// ---------------------------------------------------------------------------
// Kernel 1: pred[b,p,n,d] = sum_q w[p,n,d,q] * x[b,p,q], stored fp16 with a
// 16B-chunk swizzle inside each p-row: chunk k of capsule n lands at slot
// (k + ((n>>1)&3)) & 3. One block per p; 4 consecutive outputs per thread so
// each b-iter does one STG.64 (4 halfs) and 4 independent FFMA2 chains.
// ---------------------------------------------------------------------------
__global__ __launch_bounds__(256) void pred_kernel(
    const float* __restrict__ x, const float* __restrict__ w) {
    const int p  = blockIdx.x;
    const int t  = threadIdx.x;
    const int e0 = 4 * t;   // first of 4 consecutive outputs

    __shared__ uint4 xs4[B][PD / 4];
    for (int e = t; e < B * (PD / 4); e += 256) {
        const int b = e >> 2, j = e & 3;
        xs4[b][j] = reinterpret_cast<const uint4*>(
                        x + ((size_t)b * P + p) * PD)[j];
    }

    unsigned long long wv[4][8];
    const unsigned long long* wp =
        reinterpret_cast<const unsigned long long*>(w + (size_t)p * (ND * PD));
#pragma unroll
    for (int j = 0; j < 4; j++)
#pragma unroll
        for (int k = 0; k < 8; k++)
            wv[j][k] = wp[(size_t)(e0 + j) * 8 + k];
    __syncthreads();

    // swizzled destination offset within the p-row (constant per thread)
    const int n    = e0 >> 5;
    const int kk   = (e0 >> 3) & 3;
    const int slot = (kk + ((n >> 1) & 3)) & 3;
    const int off  = n * 64 + slot * 16 + (e0 & 7) * 2;   // 8B-aligned

    for (int b = 0; b < B; b++) {
        unsigned long long xb[8];
#pragma unroll
        for (int j = 0; j < 4; j++) {
            uint4 q = xs4[b][j];
            xb[2 * j]     = *reinterpret_cast<unsigned long long*>(&q.x);
            xb[2 * j + 1] = *reinterpret_cast<unsigned long long*>(&q.z);
        }
        float r[4];
#pragma unroll
        for (int j = 0; j < 4; j++) {
            unsigned long long acc = 0ull;
#pragma unroll
            for (int k = 0; k < 8; k++) acc = fma_f32x2(wv[j][k], xb[k], acc);
            float2 f = *reinterpret_cast<float2*>(&acc);
            r[j] = f.x + f.y;
        }
        __half2 h0 = __floats2half2_rn(r[0], r[1]);
        __half2 h1 = __floats2half2_rn(r[2], r[3]);
        uint2 pk;
        pk.x = *reinterpret_cast<unsigned*>(&h0);
        pk.y = *reinterpret_cast<unsigned*>(&h1);
        char* dst = reinterpret_cast<char*>(g_pred) +
                    ((size_t)b * P + p) * ROWB + off;
        __stcs(reinterpret_cast<float2*>(dst), *reinterpret_cast<float2*>(&pk));
    }
}

// ---------------------------------------------------------------------------
// Kernel 2: fused routing pass. Block = (chunk, b). The 64-p chunk streams
// through a 3-buffer x 32KB smem ring via cp.async.bulk: 3 copies issued up
// front, each buffer refilled right after its stage's compute, so ~2 copies
// stay in flight. Warp w handles p_local = s*16 + w*2 + {0,1}. Lane n reads
// its capsule's 64B (4x LDS.128, swizzle-rotated -> conflict-free), computes
// the lane-local agreement dot with v[n][:] (regs), intra-warp softmax over
// N, and accumulates c*pred into acc[32].
// ---------------------------------------------------------------------------
extern __shared__ char dsm[];
__global__ __launch_bounds__(256, 2) void pass_kernel(int iter) {
    const int chunk = blockIdx.x;
    const int b     = blockIdx.y;
    const int t     = threadIdx.x;
    const int w     = t >> 5;
    const int lane  = t & 31;
    const int rot   = (lane >> 1) & 3;

    const uint32_t smem_base = smem_u32(dsm);
    const uint32_t mbar_base = smem_base + NBUF * STAGE_BYTES;

    if (t == 0)
        for (int i = 0; i < NBUF; i++) mbar_init(mbar_base + 8 * i, 1);
    __syncthreads();

    const char* gsrc = reinterpret_cast<const char*>(g_pred) +
                       ((size_t)b * P + (size_t)chunk * CH) * ROWB;
    if (t == 0) {
#pragma unroll
        for (int s = 0; s < NBUF; s++) {
            mbar_expect_tx(mbar_base + 8 * s, STAGE_BYTES);
            bulk_g2s(smem_base + s * STAGE_BYTES,
                     gsrc + (size_t)s * STAGE_BYTES, STAGE_BYTES,
                     mbar_base + 8 * s);
        }
    }

    float v[32];
    if (iter > 0) {
        const float4* vp = reinterpret_cast<const float4*>(
            g_v + (size_t)b * ND + (size_t)lane * 32);
#pragma unroll
        for (int j = 0; j < 8; j++) {
            float4 q = vp[j];
            v[4 * j] = q.x; v[4 * j + 1] = q.y;
            v[4 * j + 2] = q.z; v[4 * j + 3] = q.w;
        }
    }

    float acc[32];
#pragma unroll
    for (int k = 0; k < 32; k++) acc[k] = 0.f;

    float* lgbase = g_logits + ((size_t)b * P + (size_t)chunk * CH) * N + lane;

#pragma unroll
    for (int s = 0; s < NSTAGE; s++) {
        const int buf = s % NBUF;
        mbar_wait(mbar_base + 8 * buf, (s / NBUF) & 1);
        const char* bufp = dsm + buf * STAGE_BYTES;

#pragma unroll
        for (int j = 0; j < 2; j++) {
            const int pl = s * STAGE_P + w * 2 + j;   // p within chunk
            const char* row = bufp + (w * 2 + j) * ROWB;

            uint4 q[4];
#pragma unroll
            for (int k = 0; k < 4; k++) {
                const int slot = (k + rot) & 3;
                q[k] = *reinterpret_cast<const uint4*>(row + lane * 64 + slot * 16);
            }

            float f[8];
            if (iter == 0) {
#pragma unroll
                for (int c = 0; c < 4; c++) {
                    unpack8(q[c], f);
#pragma unroll
                    for (int k = 0; k < 8; k++) acc[8 * c + k] += f[k];
                }
            } else {
                float a0 = 0.f, a1 = 0.f, a2 = 0.f, a3 = 0.f;
                float fl[32];
#pragma unroll
                for (int c = 0; c < 4; c++) unpack8(q[c], fl + 8 * c);
#pragma unroll
                for (int k = 0; k < 8; k++) {
                    a0 = fmaf(fl[k],      v[k],      a0);
                    a1 = fmaf(fl[8 + k],  v[8 + k],  a1);
                    a2 = fmaf(fl[16 + k], v[16 + k], a2);
                    a3 = fmaf(fl[24 + k], v[24 + k], a3);
                }
                float lg = (a0 + a1) + (a2 + a3);
                float* lgp = lgbase + (size_t)pl * N;
                if (iter >= 2) lg += *lgp;
                if (iter <= 2) *lgp = lg;

                const float ex = __expf(lg);
                float se = ex;
#pragma unroll
                for (int o = 16; o > 0; o >>= 1)
                    se += __shfl_xor_sync(0xffffffffu, se, o);
                const float c = __fdividef(ex, se);
#pragma unroll
                for (int k = 0; k < 32; k++) acc[k] = fmaf(c, fl[k], acc[k]);
            }
        }
        __syncthreads();   // all warps done with this buffer
        if (t == 0 && s + NBUF < NSTAGE) {
            mbar_expect_tx(mbar_base + 8 * buf, STAGE_BYTES);
            bulk_g2s(smem_base + buf * STAGE_BYTES,
                     gsrc + (size_t)(s + NBUF) * STAGE_BYTES, STAGE_BYTES,
                     mbar_base + 8 * buf);
        }
    }

    // cross-warp reduction; wsum overlaps the (now idle) stage buffers.
    // layout: wsum[w][d][n] at float index w*1056 + d*33 + n (conflict-free)
    float* wsum = reinterpret_cast<float*>(dsm);
    const float scale = (iter == 0) ? (1.f / (float)N) : 1.f;
    float* ws = wsum + w * 1056 + lane;
#pragma unroll
    for (int d = 0; d < 32; d++) ws[d * 33] = acc[d] * scale;
    __syncthreads();

    float* op = g_partial + ((size_t)b * NCH + chunk) * ND;
#pragma unroll
    for (int jj = 0; jj < 4; jj++) {
        const int e = t + 256 * jj;
        const int n = e >> 5, d = e & 31;
        float sv = 0.f;
#pragma unroll
        for (int ww = 0; ww < 8; ww++) sv += wsum[ww * 1056 + d * 33 + n];
        op[e] = sv;
    }
}

// ---------------------------------------------------------------------------
// Kernel 3: reduce partials over chunks, squash over D, write v (or d_out).
// Grid (B, 4): block (b,g) handles 256 elements e = g*256 + t.
// ---------------------------------------------------------------------------
__global__ __launch_bounds__(256) void reduce_squash_kernel(
    float* __restrict__ out, int is_final) {
    const int b = blockIdx.x;
    const int g = blockIdx.y;
    const int t = threadIdx.x;
    const int e = g * 256 + t;

    float s = 0.f;
    const float* pp = g_partial + (size_t)b * NCH * ND + e;
#pragma unroll
    for (int ch = 0; ch < NCH; ch++) s += pp[(size_t)ch * ND];

    float q = s * s;
#pragma unroll
    for (int o = 16; o > 0; o >>= 1)
        q += __shfl_xor_sync(0xffffffffu, q, o);
    const float EPS = 1e-7f;
    const float k = q / ((1.f + q) * sqrtf(q + EPS));

    float* dst = is_final ? (out + (size_t)b * ND) : (g_v + (size_t)b * ND);
    dst[e] = s * k;
}

// ---------------------------------------------------------------------------
extern "C" void kernel_launch(void* const* d_in, const int* in_sizes, int n_in,
                              void* d_out, int out_size) {
    const float* x = (const float*)d_in[0];
    const float* w = (const float*)d_in[1];
    if (n_in >= 2 && in_sizes[0] > in_sizes[1]) {
        const float* tmp = x; x = w; w = tmp;
    }
    float* out = (float*)d_out;

    const int dyn = NBUF * STAGE_BYTES + 8 * NBUF;   // bufs + mbarriers
    cudaFuncSetAttribute(pass_kernel,
                         cudaFuncAttributeMaxDynamicSharedMemorySize, dyn);

    pred_kernel<<<P, 256>>>(x, w);
    for (int it = 0; it < 4; it++) {
        pass_kernel<<<dim3(NCH, B), 256, dyn>>>(it);
        reduce_squash_kernel<<<dim3(B, 4), 256>>>(out, it == 3 ? 1 : 0);
    }
}

// round 6
// speedup vs baseline: 2.2443x; 1.0804x over previous
#include <cuda_runtime.h>
#include <cuda_fp16.h>
#include <cstdint>
#include <cstddef>

// Problem constants
#define B   64
#define P   2048
#define PD  16
#define N   32
#define D   32
#define ND  1024          // N*D
#define CH  128           // p's per chunk in pass kernel
#define NCH 16            // P / CH
#define ROWB 2048         // bytes per p-row of pred (1024 halfs)
#define STAGE_P 16
#define STAGE_BYTES (STAGE_P * ROWB)   // 32768
#define NBUF 3
#define NSTAGE 8          // CH / STAGE_P

// Scratch (device globals: allocation-free per harness rules)
__device__ __half  g_pred[(size_t)B * P * ND];        // 268 MB (fp16, swizzled rows)
__device__ float   g_logits[(size_t)B * P * N];       // 16 MB
__device__ float   g_v[(size_t)B * ND];               // 256 KB
__device__ float   g_partial[(size_t)B * NCH * ND];   // 4 MB

__device__ __forceinline__ unsigned long long fma_f32x2(
    unsigned long long a, unsigned long long b, unsigned long long c) {
    unsigned long long d;
    asm("fma.rn.f32x2 %0, %1, %2, %3;" : "=l"(d) : "l"(a), "l"(b), "l"(c));
    return d;
}
__device__ __forceinline__ unsigned long long add_f32x2(
    unsigned long long a, unsigned long long b) {
    unsigned long long d;
    asm("add.rn.f32x2 %0, %1, %2;" : "=l"(d) : "l"(a), "l"(b));
    return d;
}

__device__ __forceinline__ uint32_t smem_u32(const void* p) {
    uint32_t a;
    asm("{ .reg .u64 t; cvta.to.shared.u64 t, %1; cvt.u32.u64 %0, t; }"
        : "=r"(a) : "l"(p));
    return a;
}

__device__ __forceinline__ void mbar_init(uint32_t mbar, uint32_t cnt) {
    asm volatile("mbarrier.init.shared.b64 [%0], %1;" :: "r"(mbar), "r"(cnt)
                 : "memory");
}
__device__ __forceinline__ void mbar_expect_tx(uint32_t mbar, uint32_t bytes) {
    asm volatile("mbarrier.arrive.expect_tx.shared.b64 _, [%0], %1;"
                 :: "r"(mbar), "r"(bytes) : "memory");
}
__device__ __forceinline__ void mbar_wait(uint32_t mbar, uint32_t parity) {
    asm volatile(
        "{\n\t"
        ".reg .pred P1;\n\t"
        "WAIT_LOOP_%=:\n\t"
        "mbarrier.try_wait.parity.acquire.cta.shared::cta.b64 P1, [%0], %1, 0x989680;\n\t"
        "@P1 bra.uni WAIT_DONE_%=;\n\t"
        "bra.uni WAIT_LOOP_%=;\n\t"
        "WAIT_DONE_%=:\n\t"
        "}"
        :: "r"(mbar), "r"(parity) : "memory");
}
__device__ __forceinline__ void bulk_g2s(uint32_t dst, const void* src,
                                         uint32_t bytes, uint32_t mbar) {
    asm volatile(
        "cp.async.bulk.shared::cluster.global.mbarrier::complete_tx::bytes "
        "[%0], [%1], %2, [%3];"
        :: "r"(dst), "l"(src), "r"(bytes), "r"(mbar) : "memory");
}

__device__ __forceinline__ void unpack8(const uint4& u, float* f) {
    const __half2* h = reinterpret_cast<const __half2*>(&u);
#pragma unroll
    for (int k = 0; k < 4; k++) {
        float2 t = __half22float2(h[k]);
        f[2 * k] = t.x; f[2 * k + 1] = t.y;
    }
}

// ---------------------------------------------------------------------------
// Kernel 1: pred[b,p,n,d] = sum_q w[p,n,d,q] * x[b,p,q], stored fp16 with a
// 16B-chunk swizzle inside each p-row (slot = (k + ((n>>1)&3)) & 3).
// 2 blocks per p, 2 outputs per thread, b-loop unrolled x2: 8 independent
// depth-4 FFMA2 chains per iteration so the serial LDS->FFMA->CVT->STG
// chain no longer dominates (pred was latency-bound, not pipe-bound).
// ---------------------------------------------------------------------------
__global__ __launch_bounds__(256) void pred_kernel(
    const float* __restrict__ x, const float* __restrict__ w) {
    const int p    = blockIdx.x >> 1;
    const int half = blockIdx.x & 1;
    const int t    = threadIdx.x;
    const int e0   = half * 512 + 2 * t;   // first of 2 consecutive outputs

    __shared__ uint4 xs4[B][PD / 4];
    for (int e = t; e < B * (PD / 4); e += 256) {
        const int b = e >> 2, j = e & 3;
        xs4[b][j] = reinterpret_cast<const uint4*>(
                        x + ((size_t)b * P + p) * PD)[j];
    }

    unsigned long long wv[2][8];
    const unsigned long long* wp =
        reinterpret_cast<const unsigned long long*>(w + (size_t)p * (ND * PD));
#pragma unroll
    for (int j = 0; j < 2; j++)
#pragma unroll
        for (int k = 0; k < 8; k++)
            wv[j][k] = wp[(size_t)(e0 + j) * 8 + k];
    __syncthreads();

    // swizzled destination offset within the p-row (constant per thread)
    const int n    = e0 >> 5;
    const int kk   = (e0 >> 3) & 3;
    const int slot = (kk + ((n >> 1) & 3)) & 3;
    const int off  = n * 64 + slot * 16 + (e0 & 7) * 2;   // 4B-aligned

    char* dst0 = reinterpret_cast<char*>(g_pred) + (size_t)p * ROWB + off;

    for (int b = 0; b < B; b += 2) {
        unsigned long long xa[8], xb[8];
#pragma unroll
        for (int j = 0; j < 4; j++) {
            uint4 qa = xs4[b][j];
            uint4 qb = xs4[b + 1][j];
            xa[2 * j]     = *reinterpret_cast<unsigned long long*>(&qa.x);
            xa[2 * j + 1] = *reinterpret_cast<unsigned long long*>(&qa.z);
            xb[2 * j]     = *reinterpret_cast<unsigned long long*>(&qb.x);
            xb[2 * j + 1] = *reinterpret_cast<unsigned long long*>(&qb.z);
        }
        // 8 independent depth-4 FFMA2 chains
        unsigned long long a0l = 0, a0h = 0, a1l = 0, a1h = 0;
        unsigned long long b0l = 0, b0h = 0, b1l = 0, b1h = 0;
#pragma unroll
        for (int k = 0; k < 4; k++) {
            a0l = fma_f32x2(wv[0][k],     xa[k],     a0l);
            a0h = fma_f32x2(wv[0][k + 4], xa[k + 4], a0h);
            a1l = fma_f32x2(wv[1][k],     xa[k],     a1l);
            a1h = fma_f32x2(wv[1][k + 4], xa[k + 4], a1h);
            b0l = fma_f32x2(wv[0][k],     xb[k],     b0l);
            b0h = fma_f32x2(wv[0][k + 4], xb[k + 4], b0h);
            b1l = fma_f32x2(wv[1][k],     xb[k],     b1l);
            b1h = fma_f32x2(wv[1][k + 4], xb[k + 4], b1h);
        }
        unsigned long long s0 = add_f32x2(a0l, a0h);
        unsigned long long s1 = add_f32x2(a1l, a1h);
        unsigned long long s2 = add_f32x2(b0l, b0h);
        unsigned long long s3 = add_f32x2(b1l, b1h);
        float2 f0 = *reinterpret_cast<float2*>(&s0);
        float2 f1 = *reinterpret_cast<float2*>(&s1);
        float2 f2 = *reinterpret_cast<float2*>(&s2);
        float2 f3 = *reinterpret_cast<float2*>(&s3);
        __half2 ha = __floats2half2_rn(f0.x + f0.y, f1.x + f1.y);
        __half2 hb = __floats2half2_rn(f2.x + f2.y, f3.x + f3.y);
        __stcs(reinterpret_cast<float*>(dst0 + (size_t)b * (P * ROWB)),
               __uint_as_float(*reinterpret_cast<unsigned*>(&ha)));
        __stcs(reinterpret_cast<float*>(dst0 + (size_t)(b + 1) * (P * ROWB)),
               __uint_as_float(*reinterpret_cast<unsigned*>(&hb)));
    }
}

// ---------------------------------------------------------------------------
// Kernel 2: fused routing pass. Block = (chunk, b), chunk = 128 p's streamed
// through a 3x32KB smem ring via cp.async.bulk (8 stages -> ring fill/drain
// amortized 2x vs CH=64). Warp w handles p_local = s*16 + w*2 + {0,1}.
// Logit LDGs for a stage are issued BEFORE its mbar_wait so their latency
// hides under the copy wait. Lane n reads its capsule's 64B (4x LDS.128,
// swizzle-rotated -> conflict-free), lane-local agreement dot with v[n][:],
// intra-warp softmax over N, acc[32] per lane.
// ---------------------------------------------------------------------------
extern __shared__ char dsm[];
__global__ __launch_bounds__(256, 2) void pass_kernel(int iter) {
    const int chunk = blockIdx.x;
    const int b     = blockIdx.y;
    const int t     = threadIdx.x;
    const int w     = t >> 5;
    const int lane  = t & 31;
    const int rot   = (lane >> 1) & 3;

    const uint32_t smem_base = smem_u32(dsm);
    const uint32_t mbar_base = smem_base + NBUF * STAGE_BYTES;

    if (t == 0)
        for (int i = 0; i < NBUF; i++) mbar_init(mbar_base + 8 * i, 1);
    __syncthreads();

    const char* gsrc = reinterpret_cast<const char*>(g_pred) +
                       ((size_t)b * P + (size_t)chunk * CH) * ROWB;
    if (t == 0) {
#pragma unroll
        for (int s = 0; s < NBUF; s++) {
            mbar_expect_tx(mbar_base + 8 * s, STAGE_BYTES);
            bulk_g2s(smem_base + s * STAGE_BYTES,
                     gsrc + (size_t)s * STAGE_BYTES, STAGE_BYTES,
                     mbar_base + 8 * s);
        }
    }

    float v[32];
    if (iter > 0) {
        const float4* vp = reinterpret_cast<const float4*>(
            g_v + (size_t)b * ND + (size_t)lane * 32);
#pragma unroll
        for (int j = 0; j < 8; j++) {
            float4 q = vp[j];
            v[4 * j] = q.x; v[4 * j + 1] = q.y;
            v[4 * j + 2] = q.z; v[4 * j + 3] = q.w;
        }
    }

    float acc[32];
#pragma unroll
    for (int k = 0; k < 32; k++) acc[k] = 0.f;

    float* lgbase = g_logits + ((size_t)b * P + (size_t)chunk * CH) * N + lane;

#pragma unroll
    for (int s = 0; s < NSTAGE; s++) {
        const int buf = s % NBUF;
        const int par = (s / NBUF) & 1;
        const int pl0 = s * STAGE_P + w * 2;

        // issue logit loads before the wait: latency hides under the copy
        float lgv0 = 0.f, lgv1 = 0.f;
        if (iter >= 2) {
            lgv0 = lgbase[(size_t)pl0 * N];
            lgv1 = lgbase[(size_t)(pl0 + 1) * N];
        }

        mbar_wait(mbar_base + 8 * buf, par);
        const char* bufp = dsm + buf * STAGE_BYTES;

#pragma unroll
        for (int j = 0; j < 2; j++) {
            const int pl = pl0 + j;
            const char* row = bufp + (w * 2 + j) * ROWB;

            uint4 q[4];
#pragma unroll
            for (int k = 0; k < 4; k++) {
                const int slot = (k + rot) & 3;
                q[k] = *reinterpret_cast<const uint4*>(row + lane * 64 + slot * 16);
            }

            float f[8];
            if (iter == 0) {
#pragma unroll
                for (int c = 0; c < 4; c++) {
                    unpack8(q[c], f);
#pragma unroll
                    for (int k = 0; k < 8; k++) acc[8 * c + k] += f[k];
                }
            } else {
                float a0 = 0.f, a1 = 0.f, a2 = 0.f, a3 = 0.f;
                float fl[32];
#pragma unroll
                for (int c = 0; c < 4; c++) unpack8(q[c], fl + 8 * c);
#pragma unroll
                for (int k = 0; k < 8; k++) {
                    a0 = fmaf(fl[k],      v[k],      a0);
                    a1 = fmaf(fl[8 + k],  v[8 + k],  a1);
                    a2 = fmaf(fl[16 + k], v[16 + k], a2);
                    a3 = fmaf(fl[24 + k], v[24 + k], a3);
                }
                float lg = (a0 + a1) + (a2 + a3);
                if (iter >= 2) lg += (j == 0 ? lgv0 : lgv1);
                if (iter <= 2) lgbase[(size_t)pl * N] = lg;

                const float ex = __expf(lg);
                float se = ex;
#pragma unroll
                for (int o = 16; o > 0; o >>= 1)
                    se += __shfl_xor_sync(0xffffffffu, se, o);
                const float c = __fdividef(ex, se);
#pragma unroll
                for (int k = 0; k < 32; k++) acc[k] = fmaf(c, fl[k], acc[k]);
            }
        }
        __syncthreads();   // all warps done with this buffer
        if (t == 0 && s + NBUF < NSTAGE) {
            mbar_expect_tx(mbar_base + 8 * buf, STAGE_BYTES);
            bulk_g2s(smem_base + buf * STAGE_BYTES,
                     gsrc + (size_t)(s + NBUF) * STAGE_BYTES, STAGE_BYTES,
                     mbar_base + 8 * buf);
        }
    }

    // cross-warp reduction; wsum overlaps the (now idle) stage buffers.
    // layout: wsum[w][d][n] at float index w*1056 + d*33 + n (conflict-free)
    float* wsum = reinterpret_cast<float*>(dsm);
    const float scale = (iter == 0) ? (1.f / (float)N) : 1.f;
    float* ws = wsum + w * 1056 + lane;
#pragma unroll
    for (int d = 0; d < 32; d++) ws[d * 33] = acc[d] * scale;
    __syncthreads();

    float* op = g_partial + ((size_t)b * NCH + chunk) * ND;
#pragma unroll
    for (int jj = 0; jj < 4; jj++) {
        const int e = t + 256 * jj;
        const int n = e >> 5, d = e & 31;
        float sv = 0.f;
#pragma unroll
        for (int ww = 0; ww < 8; ww++) sv += wsum[ww * 1056 + d * 33 + n];
        op[e] = sv;
    }
}

// ---------------------------------------------------------------------------
// Kernel 3: reduce partials over chunks, squash over D, write v (or d_out).
// Grid (B, 4): block (b,g) handles 256 elements e = g*256 + t.
// ---------------------------------------------------------------------------
__global__ __launch_bounds__(256) void reduce_squash_kernel(
    float* __restrict__ out, int is_final) {
    const int b = blockIdx.x;
    const int g = blockIdx.y;
    const int t = threadIdx.x;
    const int e = g * 256 + t;

    float s = 0.f;
    const float* pp = g_partial + (size_t)b * NCH * ND + e;
#pragma unroll
    for (int ch = 0; ch < NCH; ch++) s += pp[(size_t)ch * ND];

    float q = s * s;
#pragma unroll
    for (int o = 16; o > 0; o >>= 1)
        q += __shfl_xor_sync(0xffffffffu, q, o);
    const float EPS = 1e-7f;
    const float k = q / ((1.f + q) * sqrtf(q + EPS));

    float* dst = is_final ? (out + (size_t)b * ND) : (g_v + (size_t)b * ND);
    dst[e] = s * k;
}

// ---------------------------------------------------------------------------
extern "C" void kernel_launch(void* const* d_in, const int* in_sizes, int n_in,
                              void* d_out, int out_size) {
    const float* x = (const float*)d_in[0];
    const float* w = (const float*)d_in[1];
    if (n_in >= 2 && in_sizes[0] > in_sizes[1]) {
        const float* tmp = x; x = w; w = tmp;
    }
    float* out = (float*)d_out;

    const int dyn = NBUF * STAGE_BYTES + 8 * NBUF;   // bufs + mbarriers
    cudaFuncSetAttribute(pass_kernel,
                         cudaFuncAttributeMaxDynamicSharedMemorySize, dyn);

    pred_kernel<<<2 * P, 256>>>(x, w);
    for (int it = 0; it < 4; it++) {
        pass_kernel<<<dim3(NCH, B), 256, dyn>>>(it);
        reduce_squash_kernel<<<dim3(B, 4), 256>>>(out, it == 3 ? 1 : 0);
    }
}

// round 7
// speedup vs baseline: 2.6374x; 1.1752x over previous
#include <cuda_runtime.h>
#include <cuda_fp16.h>
#include <cstdint>
#include <cstddef>

// Problem constants
#define B   64
#define P   2048
#define PD  16
#define N   32
#define D   32
#define ND  1024          // N*D
#define CH  128           // p's per chunk in pass kernel
#define NCH 16            // P / CH
#define ROWB 2048         // bytes per p-row of pred (1024 halfs)
#define STAGE_P 16
#define STAGE_BYTES (STAGE_P * ROWB)   // 32768
#define NBUF 3
#define NSTAGE 8          // CH / STAGE_P

// pred kernel smem layout (bytes)
#define WST_BYTES (1024 * 48)            // w stage: [e][24 halfs] rows (48B, padded)
#define XST_BYTES (64 * 48)              // x stage: [b][24 halfs] rows
#define CST_ROWB  144                    // c stage row: 72 halfs (64 + 8 pad)
#define CST_WARP  (16 * CST_ROWB)        // 2304B per warp
#define PRED_SMEM (WST_BYTES + XST_BYTES + 8 * CST_WARP)

// Scratch (device globals: allocation-free per harness rules)
__device__ __half  g_pred[(size_t)B * P * ND];        // 268 MB (fp16, swizzled rows)
__device__ float   g_logits[(size_t)B * P * N];       // 16 MB
__device__ float   g_v[(size_t)B * ND];               // 256 KB
__device__ float   g_partial[(size_t)B * NCH * ND];   // 4 MB

__device__ __forceinline__ uint32_t smem_u32(const void* p) {
    uint32_t a;
    asm("{ .reg .u64 t; cvta.to.shared.u64 t, %1; cvt.u32.u64 %0, t; }"
        : "=r"(a) : "l"(p));
    return a;
}

__device__ __forceinline__ void mbar_init(uint32_t mbar, uint32_t cnt) {
    asm volatile("mbarrier.init.shared.b64 [%0], %1;" :: "r"(mbar), "r"(cnt)
                 : "memory");
}
__device__ __forceinline__ void mbar_expect_tx(uint32_t mbar, uint32_t bytes) {
    asm volatile("mbarrier.arrive.expect_tx.shared.b64 _, [%0], %1;"
                 :: "r"(mbar), "r"(bytes) : "memory");
}
__device__ __forceinline__ void mbar_wait(uint32_t mbar, uint32_t parity) {
    asm volatile(
        "{\n\t"
        ".reg .pred P1;\n\t"
        "WAIT_LOOP_%=:\n\t"
        "mbarrier.try_wait.parity.acquire.cta.shared::cta.b64 P1, [%0], %1, 0x989680;\n\t"
        "@P1 bra.uni WAIT_DONE_%=;\n\t"
        "bra.uni WAIT_LOOP_%=;\n\t"
        "WAIT_DONE_%=:\n\t"
        "}"
        :: "r"(mbar), "r"(parity) : "memory");
}
__device__ __forceinline__ void bulk_g2s(uint32_t dst, const void* src,
                                         uint32_t bytes, uint32_t mbar) {
    asm volatile(
        "cp.async.bulk.shared::cluster.global.mbarrier::complete_tx::bytes "
        "[%0], [%1], %2, [%3];"
        :: "r"(dst), "l"(src), "r"(bytes), "r"(mbar) : "memory");
}

__device__ __forceinline__ void unpack8(const uint4& u, float* f) {
    const __half2* h = reinterpret_cast<const __half2*>(&u);
#pragma unroll
    for (int k = 0; k < 4; k++) {
        float2 t = __half22float2(h[k]);
        f[2 * k] = t.x; f[2 * k + 1] = t.y;
    }
}

// mma.sync helpers
__device__ __forceinline__ void ldsm_x4(uint32_t* r, uint32_t addr) {
    asm volatile("ldmatrix.sync.aligned.m8n8.x4.shared.b16 {%0,%1,%2,%3}, [%4];"
        : "=r"(r[0]), "=r"(r[1]), "=r"(r[2]), "=r"(r[3]) : "r"(addr));
}
__device__ __forceinline__ void ldsm_x2(uint32_t* r, uint32_t addr) {
    asm volatile("ldmatrix.sync.aligned.m8n8.x2.shared.b16 {%0,%1}, [%2];"
        : "=r"(r[0]), "=r"(r[1]) : "r"(addr));
}
__device__ __forceinline__ void stsm_x4(uint32_t addr, uint32_t r0, uint32_t r1,
                                        uint32_t r2, uint32_t r3) {
    asm volatile("stmatrix.sync.aligned.m8n8.x4.shared.b16 [%0], {%1,%2,%3,%4};"
        :: "r"(addr), "r"(r0), "r"(r1), "r"(r2), "r"(r3) : "memory");
}
__device__ __forceinline__ void mma16816(float* d, const uint32_t* a,
                                         const uint32_t* b) {
    asm volatile(
        "mma.sync.aligned.m16n8k16.row.col.f32.f16.f16.f32 "
        "{%0,%1,%2,%3}, {%4,%5,%6,%7}, {%8,%9}, {%10,%11,%12,%13};"
        : "=f"(d[0]), "=f"(d[1]), "=f"(d[2]), "=f"(d[3])
        : "r"(a[0]), "r"(a[1]), "r"(a[2]), "r"(a[3]),
          "r"(b[0]), "r"(b[1]),
          "f"(0.f), "f"(0.f), "f"(0.f), "f"(0.f));
}

extern __shared__ char dsm[];

// ---------------------------------------------------------------------------
// Kernel 1 (HMMA): pred[b,p,:] = X_p[b,q] * W_p[q,e], fp16 in / fp32 accum,
// stored fp16 with the 16B-chunk swizzle (slot = (k + ((n>>1)&3)) & 3).
// Block per p, 8 warps. Stages w as [e][24h] rows (48B, padded) and x as
// [b][24h]; A = x via ldmatrix.x4 (row-major m16k16), B = w rows via plain
// ldmatrix.x2 ([n][k] rows == col-major k16n8). C fragments -> half2 ->
// stmatrix into a padded per-warp stage -> swizzle-aware uint4 copy to gmem.
// ---------------------------------------------------------------------------
__global__ __launch_bounds__(256, 2) void pred_kernel(
    const float* __restrict__ x, const float* __restrict__ w) {
    const int p    = blockIdx.x;
    const int t    = threadIdx.x;
    const int wp   = t >> 5;
    const int lane = t & 31;

    __half* wst = reinterpret_cast<__half*>(dsm);
    __half* xst = reinterpret_cast<__half*>(dsm + WST_BYTES);
    char*   cst = dsm + WST_BYTES + XST_BYTES;

    const uint32_t sbase    = smem_u32(dsm);
    const uint32_t wst_addr = sbase;
    const uint32_t xst_addr = sbase + WST_BYTES;
    const uint32_t cst_addr = sbase + WST_BYTES + XST_BYTES;

    // stage w (fp32 -> fp16), coalesced: 4096 uint4 over 256 threads
    {
        const float4* wrow = reinterpret_cast<const float4*>(
            w + (size_t)p * (ND * PD));
#pragma unroll
        for (int i = 0; i < 16; i++) {
            const int idx = t + 256 * i;
            const int e = idx >> 2, qb = idx & 3;
            float4 v = wrow[idx];
            __half2 h0 = __floats2half2_rn(v.x, v.y);
            __half2 h1 = __floats2half2_rn(v.z, v.w);
            uint2 pk;
            pk.x = *reinterpret_cast<unsigned*>(&h0);
            pk.y = *reinterpret_cast<unsigned*>(&h1);
            *reinterpret_cast<uint2*>(
                reinterpret_cast<char*>(wst) + e * 48 + qb * 8) = pk;
        }
    }
    // stage x: 256 uint4, one per thread
    {
        const int b = t >> 2, qb = t & 3;
        float4 v = reinterpret_cast<const float4*>(
            x + ((size_t)b * P + p) * PD)[qb];
        __half2 h0 = __floats2half2_rn(v.x, v.y);
        __half2 h1 = __floats2half2_rn(v.z, v.w);
        uint2 pk;
        pk.x = *reinterpret_cast<unsigned*>(&h0);
        pk.y = *reinterpret_cast<unsigned*>(&h1);
        *reinterpret_cast<uint2*>(
            reinterpret_cast<char*>(xst) + b * 48 + qb * 8) = pk;
    }
    __syncthreads();

    // A fragments: all 64 b's (4 m-tiles), loaded once
    uint32_t afr[4][4];
#pragma unroll
    for (int mt = 0; mt < 4; mt++) {
        const int mat = lane >> 3, r = lane & 7;
        const uint32_t addr = xst_addr +
            (16 * mt + (mat & 1) * 8 + r) * 48 + (mat >> 1) * 16;
        ldsm_x4(afr[mt], addr);
    }

    const uint32_t cw = cst_addr + wp * CST_WARP;

#pragma unroll
    for (int eg = 0; eg < 2; eg++) {
        const int ebase = wp * 128 + eg * 64;

        // B fragments: 8 n-tiles of 8 e's
        uint32_t bfr[8][2];
#pragma unroll
        for (int j = 0; j < 8; j++) {
            const uint32_t addr = wst_addr +
                (ebase + 8 * j + (lane & 7)) * 48 + ((lane >> 3) & 1) * 16;
            ldsm_x2(bfr[j], addr);
        }

#pragma unroll
        for (int mt = 0; mt < 4; mt++) {
            float c[8][4];
#pragma unroll
            for (int j = 0; j < 8; j++) mma16816(c[j], afr[mt], bfr[j]);

            uint32_t h[8][2];
#pragma unroll
            for (int j = 0; j < 8; j++) {
                __half2 lo = __floats2half2_rn(c[j][0], c[j][1]);
                __half2 hi = __floats2half2_rn(c[j][2], c[j][3]);
                h[j][0] = *reinterpret_cast<unsigned*>(&lo);
                h[j][1] = *reinterpret_cast<unsigned*>(&hi);
            }

            // stmatrix: 16 8x8 mats = (2 row-groups) x (8 e-blocks)
            const int r7 = lane & 7, m3 = lane >> 3;
            stsm_x4(cw + r7 * CST_ROWB + m3 * 16,
                    h[0][0], h[1][0], h[2][0], h[3][0]);
            stsm_x4(cw + r7 * CST_ROWB + (4 + m3) * 16,
                    h[4][0], h[5][0], h[6][0], h[7][0]);
            stsm_x4(cw + (r7 + 8) * CST_ROWB + m3 * 16,
                    h[0][1], h[1][1], h[2][1], h[3][1]);
            stsm_x4(cw + (r7 + 8) * CST_ROWB + (4 + m3) * 16,
                    h[4][1], h[5][1], h[6][1], h[7][1]);
            __syncwarp();

            // copy out with swizzle: lane -> (b-row, capsule)
            const int bl = lane >> 1, cap = lane & 1;
            const int n  = wp * 4 + eg * 2 + cap;
            const int rot = (n >> 1) & 3;
            const int b   = 16 * mt + bl;
            char* gdst = reinterpret_cast<char*>(g_pred) +
                         ((size_t)b * P + p) * ROWB + n * 64;
            const char* csrc = cst + wp * CST_WARP + bl * CST_ROWB + cap * 64;
#pragma unroll
            for (int k = 0; k < 4; k++) {
                uint4 v = *reinterpret_cast<const uint4*>(csrc + k * 16);
                __stcs(reinterpret_cast<uint4*>(gdst + ((k + rot) & 3) * 16), v);
            }
            __syncwarp();
        }
    }
}

// ---------------------------------------------------------------------------
// Kernel 2: fused routing pass (unchanged from R6). Block = (chunk, b),
// 128 p's streamed through a 3x32KB smem ring via cp.async.bulk. Warp w
// handles p_local = s*16 + w*2 + {0,1}; lane n reads its capsule's 64B
// (4x LDS.128, swizzle-rotated), lane-local agreement dot with v[n][:],
// intra-warp softmax over N, acc[32] per lane.
// ---------------------------------------------------------------------------
__global__ __launch_bounds__(256, 2) void pass_kernel(int iter) {
    const int chunk = blockIdx.x;
    const int b     = blockIdx.y;
    const int t     = threadIdx.x;
    const int w     = t >> 5;
    const int lane  = t & 31;
    const int rot   = (lane >> 1) & 3;

    const uint32_t smem_base = smem_u32(dsm);
    const uint32_t mbar_base = smem_base + NBUF * STAGE_BYTES;

    if (t == 0)
        for (int i = 0; i < NBUF; i++) mbar_init(mbar_base + 8 * i, 1);
    __syncthreads();

    const char* gsrc = reinterpret_cast<const char*>(g_pred) +
                       ((size_t)b * P + (size_t)chunk * CH) * ROWB;
    if (t == 0) {
#pragma unroll
        for (int s = 0; s < NBUF; s++) {
            mbar_expect_tx(mbar_base + 8 * s, STAGE_BYTES);
            bulk_g2s(smem_base + s * STAGE_BYTES,
                     gsrc + (size_t)s * STAGE_BYTES, STAGE_BYTES,
                     mbar_base + 8 * s);
        }
    }

    float v[32];
    if (iter > 0) {
        const float4* vp = reinterpret_cast<const float4*>(
            g_v + (size_t)b * ND + (size_t)lane * 32);
#pragma unroll
        for (int j = 0; j < 8; j++) {
            float4 q = vp[j];
            v[4 * j] = q.x; v[4 * j + 1] = q.y;
            v[4 * j + 2] = q.z; v[4 * j + 3] = q.w;
        }
    }

    float acc[32];
#pragma unroll
    for (int k = 0; k < 32; k++) acc[k] = 0.f;

    float* lgbase = g_logits + ((size_t)b * P + (size_t)chunk * CH) * N + lane;

#pragma unroll
    for (int s = 0; s < NSTAGE; s++) {
        const int buf = s % NBUF;
        const int par = (s / NBUF) & 1;
        const int pl0 = s * STAGE_P + w * 2;

        float lgv0 = 0.f, lgv1 = 0.f;
        if (iter >= 2) {
            lgv0 = lgbase[(size_t)pl0 * N];
            lgv1 = lgbase[(size_t)(pl0 + 1) * N];
        }

        mbar_wait(mbar_base + 8 * buf, par);
        const char* bufp = dsm + buf * STAGE_BYTES;

#pragma unroll
        for (int j = 0; j < 2; j++) {
            const int pl = pl0 + j;
            const char* row = bufp + (w * 2 + j) * ROWB;

            uint4 q[4];
#pragma unroll
            for (int k = 0; k < 4; k++) {
                const int slot = (k + rot) & 3;
                q[k] = *reinterpret_cast<const uint4*>(row + lane * 64 + slot * 16);
            }

            float f[8];
            if (iter == 0) {
#pragma unroll
                for (int c = 0; c < 4; c++) {
                    unpack8(q[c], f);
#pragma unroll
                    for (int k = 0; k < 8; k++) acc[8 * c + k] += f[k];
                }
            } else {
                float a0 = 0.f, a1 = 0.f, a2 = 0.f, a3 = 0.f;
                float fl[32];
#pragma unroll
                for (int c = 0; c < 4; c++) unpack8(q[c], fl + 8 * c);
#pragma unroll
                for (int k = 0; k < 8; k++) {
                    a0 = fmaf(fl[k],      v[k],      a0);
                    a1 = fmaf(fl[8 + k],  v[8 + k],  a1);
                    a2 = fmaf(fl[16 + k], v[16 + k], a2);
                    a3 = fmaf(fl[24 + k], v[24 + k], a3);
                }
                float lg = (a0 + a1) + (a2 + a3);
                if (iter >= 2) lg += (j == 0 ? lgv0 : lgv1);
                if (iter <= 2) lgbase[(size_t)pl * N] = lg;

                const float ex = __expf(lg);
                float se = ex;
#pragma unroll
                for (int o = 16; o > 0; o >>= 1)
                    se += __shfl_xor_sync(0xffffffffu, se, o);
                const float c = __fdividef(ex, se);
#pragma unroll
                for (int k = 0; k < 32; k++) acc[k] = fmaf(c, fl[k], acc[k]);
            }
        }
        __syncthreads();
        if (t == 0 && s + NBUF < NSTAGE) {
            mbar_expect_tx(mbar_base + 8 * buf, STAGE_BYTES);
            bulk_g2s(smem_base + buf * STAGE_BYTES,
                     gsrc + (size_t)(s + NBUF) * STAGE_BYTES, STAGE_BYTES,
                     mbar_base + 8 * buf);
        }
    }

    // cross-warp reduction in smem (overlaps idle stage buffers)
    float* wsum = reinterpret_cast<float*>(dsm);
    const float scale = (iter == 0) ? (1.f / (float)N) : 1.f;
    float* ws = wsum + w * 1056 + lane;
#pragma unroll
    for (int d = 0; d < 32; d++) ws[d * 33] = acc[d] * scale;
    __syncthreads();

    float* op = g_partial + ((size_t)b * NCH + chunk) * ND;
#pragma unroll
    for (int jj = 0; jj < 4; jj++) {
        const int e = t + 256 * jj;
        const int n = e >> 5, d = e & 31;
        float sv = 0.f;
#pragma unroll
        for (int ww = 0; ww < 8; ww++) sv += wsum[ww * 1056 + d * 33 + n];
        op[e] = sv;
    }
}

// ---------------------------------------------------------------------------
// Kernel 3: reduce partials over chunks, squash over D, write v (or d_out).
// ---------------------------------------------------------------------------
__global__ __launch_bounds__(256) void reduce_squash_kernel(
    float* __restrict__ out, int is_final) {
    const int b = blockIdx.x;
    const int g = blockIdx.y;
    const int t = threadIdx.x;
    const int e = g * 256 + t;

    float s = 0.f;
    const float* pp = g_partial + (size_t)b * NCH * ND + e;
#pragma unroll
    for (int ch = 0; ch < NCH; ch++) s += pp[(size_t)ch * ND];

    float q = s * s;
#pragma unroll
    for (int o = 16; o > 0; o >>= 1)
        q += __shfl_xor_sync(0xffffffffu, q, o);
    const float EPS = 1e-7f;
    const float k = q / ((1.f + q) * sqrtf(q + EPS));

    float* dst = is_final ? (out + (size_t)b * ND) : (g_v + (size_t)b * ND);
    dst[e] = s * k;
}

// ---------------------------------------------------------------------------
extern "C" void kernel_launch(void* const* d_in, const int* in_sizes, int n_in,
                              void* d_out, int out_size) {
    const float* x = (const float*)d_in[0];
    const float* w = (const float*)d_in[1];
    if (n_in >= 2 && in_sizes[0] > in_sizes[1]) {
        const float* tmp = x; x = w; w = tmp;
    }
    float* out = (float*)d_out;

    const int dyn_pass = NBUF * STAGE_BYTES + 8 * NBUF;
    cudaFuncSetAttribute(pass_kernel,
                         cudaFuncAttributeMaxDynamicSharedMemorySize, dyn_pass);
    cudaFuncSetAttribute(pred_kernel,
                         cudaFuncAttributeMaxDynamicSharedMemorySize, PRED_SMEM);

    pred_kernel<<<P, 256, PRED_SMEM>>>(x, w);
    for (int it = 0; it < 4; it++) {
        pass_kernel<<<dim3(NCH, B), 256, dyn_pass>>>(it);
        reduce_squash_kernel<<<dim3(B, 4), 256>>>(out, it == 3 ? 1 : 0);
    }
}